// round 13
// baseline (speedup 1.0000x reference)
#include <cuda_runtime.h>
#include <cstdint>

#define DI __device__ __forceinline__

// ---------------- problem constants ----------------
constexpr int NB   = 512;                 // nodes
constexpr int TT   = 24;                  // T
constexpr int HIDC = 256;
constexpr int HORC = 24;
constexpr int NIDC = 64;
constexpr int DD   = TT + NB * TT + NIDC; // 12376
constexpr int DP   = 12384;               // padded to /16
constexpr int MM   = 8 * NB;              // 4096 rows
constexpr int SPLIT_MAX = 8;
constexpr int CAPR = 4096;                // sparse entries cap per row

// ---------------- scratch (__device__ globals; no allocs) ----------------
__device__ float g_x   [(size_t)MM * DP];               // ~203 MB
__device__ float g_bc  [(size_t)MM * DP];               // ~203 MB
__device__ float g_part[(size_t)SPLIT_MAX * MM * HIDC]; // 33.5 MB split-K partials
__device__ int   g_scol[(size_t)MM * CAPR];             // 67 MB sparse cols
__device__ float g_sval[(size_t)MM * CAPR];             // 67 MB sparse vals
__device__ int   g_scnt[MM];
__device__ float g_hA[MM * HIDC];
__device__ float g_hB[MM * HIDC];
__device__ float g_F [MM * HORC];
__device__ float g_level[MM];

// ---------------- helpers ----------------
DI float tf32r(float x) {                 // round-to-nearest TF32 (keep fp32 container)
    unsigned o;
    asm("cvt.rna.tf32.f32 %0, %1;" : "=r"(o) : "f"(x));
    return __uint_as_float(o);
}

DI void mma8(float c[4], const unsigned a[4], const unsigned b[2]) {
    asm volatile(
        "mma.sync.aligned.m16n8k8.row.col.f32.tf32.tf32.f32 "
        "{%0,%1,%2,%3}, {%4,%5,%6,%7}, {%8,%9}, {%0,%1,%2,%3};\n"
        : "+f"(c[0]), "+f"(c[1]), "+f"(c[2]), "+f"(c[3])
        : "r"(a[0]), "r"(a[1]), "r"(a[2]), "r"(a[3]),
          "r"(b[0]), "r"(b[1]));
}

DI void ldsm4(unsigned r[4], uint32_t addr) {
    asm volatile("ldmatrix.sync.aligned.m8n8.x4.shared.b16 {%0,%1,%2,%3}, [%4];"
                 : "=r"(r[0]), "=r"(r[1]), "=r"(r[2]), "=r"(r[3]) : "r"(addr));
}

// ---------------- build x = concat(hist/level, relu(adj*hist/level - 1), emb) ----------------
// Computes level/inv inline (prep merged), and deterministically compacts the
// nonzeros of the mid region into per-row lists.
__global__ __launch_bounds__(256) void build_x_kernel(
        const float* __restrict__ hist, const int* __restrict__ nid,
        const float* __restrict__ adj,  const float* __restrict__ emb) {
    int r = blockIdx.x;                       // (b,n) row
    const int tid = threadIdx.x;
    const float* adjr  = adj  + (size_t)r * NB;
    const float* histb = hist + (size_t)(r >> 9) * NB * TT;
    const float* histr = hist + (size_t)r * TT;
    float* xr = g_x + (size_t)r * DP;

    // level = max_t hist[r, t];  inv = div_no_nan
    __shared__ float s_inv;
    if (tid < 32) {
        float v = (tid < TT) ? histr[tid] : -1e30f;
#pragma unroll
        for (int off = 16; off > 0; off >>= 1)
            v = fmaxf(v, __shfl_xor_sync(0xffffffffu, v, off));
        if (tid == 0) {
            g_level[r] = v;
            s_inv = (v != 0.0f) ? (1.0f / v) : 0.0f;
        }
    }
    __syncthreads();
    const float inv = s_inv;
    int nodeid = nid[r];

    for (int c4 = tid; c4 < DP / 4; c4 += blockDim.x) {
        int c = c4 * 4;
        float4 v;
        if (c < TT) {
            v.x = histr[c] * inv; v.y = histr[c + 1] * inv;
            v.z = histr[c + 2] * inv; v.w = histr[c + 3] * inv;
        } else if (c < TT + NB * TT) {
            int u  = c - TT;
            int m  = u / TT;                  // 4-elem group never crosses m (24 % 4 == 0)
            int t0 = u - m * TT;
            float a = adjr[m];
            const float* hm = histb + m * TT + t0;
            v.x = fmaxf(fmaf(a * hm[0], inv, -1.0f), 0.0f);
            v.y = fmaxf(fmaf(a * hm[1], inv, -1.0f), 0.0f);
            v.z = fmaxf(fmaf(a * hm[2], inv, -1.0f), 0.0f);
            v.w = fmaxf(fmaf(a * hm[3], inv, -1.0f), 0.0f);
        } else if (c < DD) {
            const float* e = emb + (size_t)nodeid * NIDC + (c - (TT + NB * TT));
            v.x = e[0]; v.y = e[1]; v.z = e[2]; v.w = e[3];
        } else {
            v.x = v.y = v.z = v.w = 0.0f;     // pad
        }
        reinterpret_cast<float4*>(xr + c)[0] = v;
    }

    // ---- deterministic sparse compaction of the mid region (12288 elems) ----
    // thread t owns mid elems [48t, 48t+48) -> cols [TT+48t, TT+48t+48)
    __shared__ int s_c[256];
    const int ub  = tid * 48;
    int ln = 0;
    for (int i = 0; i < 48; i++) {
        int m = 2 * tid + (i >= 24 ? 1 : 0);
        int t = (i >= 24) ? i - 24 : i;
        float v = fmaxf(fmaf(adjr[m] * histb[m * TT + t], inv, -1.0f), 0.0f);
        ln += (v > 0.0f) ? 1 : 0;
    }
    s_c[tid] = ln;
    __syncthreads();
    // Hillis-Steele inclusive scan
    for (int off = 1; off < 256; off <<= 1) {
        int add = (tid >= off) ? s_c[tid - off] : 0;
        __syncthreads();
        s_c[tid] += add;
        __syncthreads();
    }
    int base = s_c[tid] - ln;
    int w = 0;
    for (int i = 0; i < 48; i++) {
        int m = 2 * tid + (i >= 24 ? 1 : 0);
        int t = (i >= 24) ? i - 24 : i;
        float v = fmaxf(fmaf(adjr[m] * histb[m * TT + t], inv, -1.0f), 0.0f);
        if (v > 0.0f) {
            int pos = base + w;
            if (pos < CAPR) {
                g_scol[(size_t)r * CAPR + pos] = TT + ub + i;
                g_sval[(size_t)r * CAPR + pos] = v;
            }
            w++;
        }
    }
    if (tid == 255) g_scnt[r] = min(s_c[255], CAPR);
}

// ---------------- block-0 input layer via sparsity: h = relu(x @ W + b) ----------------
__global__ __launch_bounds__(128) void fc0_kernel(
        const float* __restrict__ x, const float* __restrict__ W,
        const float* __restrict__ bias, float* __restrict__ out) {
    const int r = blockIdx.x, tid = threadIdx.x;
    __shared__ float sx[88];
    __shared__ int   scc[128];
    __shared__ float svv[128];
    if (tid < 24)       sx[tid] = x[(size_t)r * DP + tid];
    else if (tid < 88)  sx[tid] = x[(size_t)r * DP + 12312 + (tid - 24)];
    __syncthreads();

    float a0 = 0.0f, a1 = 0.0f;
#pragma unroll 8
    for (int j = 0; j < 88; j++) {
        int c = (j < 24) ? j : 12312 + (j - 24);
        float xv = sx[j];
        a0 = fmaf(xv, W[(size_t)c * HIDC + tid],       a0);
        a1 = fmaf(xv, W[(size_t)c * HIDC + tid + 128], a1);
    }
    const int cnt = g_scnt[r];
    for (int bse = 0; bse < cnt; bse += 128) {
        __syncthreads();
        if (bse + tid < cnt) {
            scc[tid] = g_scol[(size_t)r * CAPR + bse + tid];
            svv[tid] = g_sval[(size_t)r * CAPR + bse + tid];
        }
        __syncthreads();
        int m = min(128, cnt - bse);
        for (int j = 0; j < m; j++) {
            float v = svv[j];
            int   c = scc[j];
            a0 = fmaf(v, W[(size_t)c * HIDC + tid],       a0);
            a1 = fmaf(v, W[(size_t)c * HIDC + tid + 128], a1);
        }
    }
    out[(size_t)r * HIDC + tid]       = fmaxf(a0 + bias[tid],       0.0f);
    out[(size_t)r * HIDC + tid + 128] = fmaxf(a1 + bias[tid + 128], 0.0f);
}

// ---------------- TF32 GEMM: C[M x Nreal] = A[M x K] * B[K x Nreal] ----------------
// EPI 0: Out = relu(acc + bias[n])            (fused; staged coalesced)
// EPI 1: Out = relu(Xin - acc - bias[n])      (backcast; staged coalesced)
// EPI 2: Out[z-slice] = acc                   (split-K partial; staged coalesced)
template <int BM, int EPI>
__global__ __launch_bounds__(256) void gemm_k(
    const float* __restrict__ A, int lda,
    const float* __restrict__ B, int ldb,
    int K, int Nreal,
    const float* __restrict__ bias,
    const float* __restrict__ Xin, int ldx,
    float* __restrict__ Out, int ldo)
{
    constexpr int BN = 128, KT = 16;
    constexpr int WM = BM / 2;                // warps 2x4 (m x n)
    constexpr int MT = WM / 16;               // mma m-tiles per warp

    constexpr int ABYTES = 2 * BM * 20 * 4;
    constexpr int BBYTES = 2 * KT * 136 * 4;
    constexpr int CBYTES = 64 * 132 * 4;      // staged-epilogue tile
    constexpr int RAWB   = (ABYTES + BBYTES > CBYTES) ? (ABYTES + BBYTES) : CBYTES;

    __shared__ __align__(16) char raw[RAWB];
    typedef float AsT[BM][20];                // KT=16 + pad 4 (LDSM-conflict-free)
    typedef float BsT[KT][136];               // 128 + pad 8
    AsT* As = reinterpret_cast<AsT*>(raw);
    BsT* Bs = reinterpret_cast<BsT*>(raw + ABYTES);
    float* Cs = reinterpret_cast<float*>(raw);  // aliases pipeline bufs; used after final sync

    const int tid  = threadIdx.x;
    const int warp = tid >> 5, lane = tid & 31;
    const int wm = warp >> 2, wn = warp & 3;
    const int gid = lane >> 2, tig = lane & 3;
    const int m0 = blockIdx.y * BM;
    const int n0 = blockIdx.x * BN;

    const int lt = lane >> 3, lr = lane & 7;
    const uint32_t aAddr0 = (uint32_t)__cvta_generic_to_shared(
        &As[0][wm * WM + lr + ((lt & 1) << 3)][(lt >> 1) << 2]);

    float acc[MT][4][4];
#pragma unroll
    for (int mi = 0; mi < MT; mi++)
#pragma unroll
        for (int ni = 0; ni < 4; ni++)
#pragma unroll
            for (int e = 0; e < 4; e++) acc[mi][ni][e] = 0.0f;

    const int arow = tid >> 2;                // 0..63
    const int akc  = (tid & 3) * 4;

    float4 aR[BM / 64], bR[2];

    auto ldg = [&](int k0) {
#pragma unroll
        for (int i = 0; i < BM / 64; i++) {
            int r = m0 + arow + i * 64;
            int k = k0 + akc;
            aR[i] = (k < K) ? *reinterpret_cast<const float4*>(A + (size_t)r * lda + k)
                            : make_float4(0.f, 0.f, 0.f, 0.f);
        }
#pragma unroll
        for (int i = 0; i < 2; i++) {
            int j = tid + i * 256;
            int kr = j >> 5, cf = (j & 31) * 4;
            int k = k0 + kr, c = n0 + cf;
            bR[i] = (k < K && c < Nreal)
                        ? *reinterpret_cast<const float4*>(B + (size_t)k * ldb + c)
                        : make_float4(0.f, 0.f, 0.f, 0.f);
        }
    };
    auto sts = [&](int p) {
#pragma unroll
        for (int i = 0; i < BM / 64; i++) {
            float4 v = aR[i];
            v.x = tf32r(v.x); v.y = tf32r(v.y); v.z = tf32r(v.z); v.w = tf32r(v.w);
            *reinterpret_cast<float4*>(&As[p][arow + i * 64][akc]) = v;
        }
#pragma unroll
        for (int i = 0; i < 2; i++) {
            int j = tid + i * 256;
            int kr = j >> 5, cf = (j & 31) * 4;
            float4 v = bR[i];
            v.x = tf32r(v.x); v.y = tf32r(v.y); v.z = tf32r(v.z); v.w = tf32r(v.w);
            *reinterpret_cast<float4*>(&Bs[p][kr][cf]) = v;
        }
    };
    auto compute = [&](int p) {
        const uint32_t ap = aAddr0 + (uint32_t)(p * (BM * 20 * 4));
#pragma unroll
        for (int sub = 0; sub < 2; sub++) {
            int kb = sub * 8;
            unsigned af[MT][4];
#pragma unroll
            for (int mi = 0; mi < MT; mi++)
                ldsm4(af[mi], ap + mi * (16 * 20 * 4) + sub * 32);
            unsigned bfr[4][2];
#pragma unroll
            for (int ni = 0; ni < 4; ni++) {
                int c = wn * 32 + ni * 8 + gid;
                bfr[ni][0] = __float_as_uint(Bs[p][kb + tig    ][c]);
                bfr[ni][1] = __float_as_uint(Bs[p][kb + tig + 4][c]);
            }
#pragma unroll
            for (int mi = 0; mi < MT; mi++)
#pragma unroll
                for (int ni = 0; ni < 4; ni++)
                    mma8(acc[mi][ni], af[mi], bfr[ni]);
        }
    };

    // split-K: partition the KT-tile range across gridDim.z
    const int nk_total = (K + KT - 1) / KT;
    const int per = (nk_total + gridDim.z - 1) / gridDim.z;
    const int kt0 = blockIdx.z * per;
    const int kt1 = min(nk_total, kt0 + per);

    ldg(kt0 * KT);
    sts(0);
    __syncthreads();
    int p = 0;
    for (int kt = kt0; kt < kt1; kt++) {
        bool nxt = (kt + 1 < kt1);
        if (nxt) ldg((kt + 1) * KT);          // overlap gmem with mma
        compute(p);
        if (nxt) sts(p ^ 1);
        __syncthreads();
        p ^= 1;
    }

    // ---------------- staged, fully-coalesced epilogue ----------------
    const size_t zoff = (EPI == 2) ? (size_t)blockIdx.z * MM * HIDC : 0;
#pragma unroll
    for (int half = 0; half < BM / 64; half++) {
        if (((wm * WM) >> 6) == half) {
#pragma unroll
            for (int mi = 0; mi < MT; mi++)
#pragma unroll
                for (int ni = 0; ni < 4; ni++)
#pragma unroll
                    for (int e = 0; e < 4; e++) {
                        int rl = wm * WM + mi * 16 + gid + ((e >> 1) << 3) - half * 64;
                        int cl = wn * 32 + ni * 8 + tig * 2 + (e & 1);
                        Cs[rl * 132 + cl] = acc[mi][ni][e];
                    }
        }
        __syncthreads();
#pragma unroll
        for (int j = 0; j < 8; j++) {
            int idx = tid + j * 256;
            int rl = idx >> 5, c4 = idx & 31;
            int row = m0 + half * 64 + rl;
            int gc  = n0 + c4 * 4;
            if (gc + 4 <= Nreal) {            // DD boundary is float4-exact
                float4 a = *reinterpret_cast<const float4*>(&Cs[rl * 132 + c4 * 4]);
                if (EPI == 0) {
                    float4 bv = *reinterpret_cast<const float4*>(bias + gc);
                    float4 r;
                    r.x = fmaxf(a.x + bv.x, 0.0f);
                    r.y = fmaxf(a.y + bv.y, 0.0f);
                    r.z = fmaxf(a.z + bv.z, 0.0f);
                    r.w = fmaxf(a.w + bv.w, 0.0f);
                    *reinterpret_cast<float4*>(Out + (size_t)row * ldo + gc) = r;
                } else if (EPI == 1) {
                    float4 xv = *reinterpret_cast<const float4*>(Xin + (size_t)row * ldx + gc);
                    float4 bv = *reinterpret_cast<const float4*>(bias + gc);
                    float4 r;
                    r.x = fmaxf(xv.x - a.x - bv.x, 0.0f);
                    r.y = fmaxf(xv.y - a.y - bv.y, 0.0f);
                    r.z = fmaxf(xv.z - a.z - bv.z, 0.0f);
                    r.w = fmaxf(xv.w - a.w - bv.w, 0.0f);
                    *reinterpret_cast<float4*>(Out + (size_t)row * ldo + gc) = r;
                } else {
                    *reinterpret_cast<float4*>(Out + zoff + (size_t)row * ldo + gc) = a;
                }
            }
        }
        __syncthreads();
    }
}

// ---------------- split-K reduce: out = relu(sum_s part[s] + bias) ----------------
__global__ void reduce_relu_kernel(const float* __restrict__ part,
                                   const float* __restrict__ bias,
                                   float* __restrict__ out, int S) {
    int idx = blockIdx.x * blockDim.x + threadIdx.x;   // float4 index over MM*HIDC/4
    const float4* p4 = reinterpret_cast<const float4*>(part);
    size_t stride4 = (size_t)MM * HIDC / 4;
    float4 a = p4[idx];
    for (int s = 1; s < S; s++) {
        float4 b = p4[idx + (size_t)s * stride4];
        a.x += b.x; a.y += b.y; a.z += b.z; a.w += b.w;
    }
    int col = (idx * 4) & (HIDC - 1);
    float4 bv = *reinterpret_cast<const float4*>(bias + col);
    float4 r;
    r.x = fmaxf(a.x + bv.x, 0.0f);
    r.y = fmaxf(a.y + bv.y, 0.0f);
    r.z = fmaxf(a.z + bv.z, 0.0f);
    r.w = fmaxf(a.w + bv.w, 0.0f);
    reinterpret_cast<float4*>(out)[idx] = r;
}

// ---------------- forecast: F (+)= h @ W_f + b_f ; final: out = F * level ----------------
__global__ void forecast_kernel(const float* __restrict__ h, const float* __restrict__ Wf,
                                const float* __restrict__ bf, int mode,
                                float* __restrict__ outF) {
    __shared__ float sW[HIDC * HORC];
    for (int i = threadIdx.x; i < HIDC * HORC; i += blockDim.x) sW[i] = Wf[i];
    __syncthreads();
    int idx = blockIdx.x * blockDim.x + threadIdx.x;   // exactly MM*HORC threads
    int r = idx / HORC, o = idx - r * HORC;
    const float* hr = h + (size_t)r * HIDC;
    float a = 0.0f;
#pragma unroll 8
    for (int k = 0; k < HIDC; k++) a = fmaf(hr[k], sW[k * HORC + o], a);
    a += bf[o];
    if (mode == 0)      g_F[idx] = a;
    else if (mode == 1) g_F[idx] += a;
    else                outF[idx] = (g_F[idx] + a) * g_level[r];
}

// ---------------- launch ----------------
extern "C" void kernel_launch(void* const* d_in, const int* in_sizes, int n_in,
                              void* d_out, int out_size) {
    const float* hist = (const float*)d_in[0];
    const int*   nid  = (const int*)  d_in[1];
    // d_in[2] = time_of_day (unused by reference)
    const float* adj  = (const float*)d_in[3];
    const float* emb  = (const float*)d_in[4];
    const float* Win  = (const float*)d_in[5];
    const float* bin  = (const float*)d_in[6];
    const float* Whid = (const float*)d_in[7];
    const float* bhid = (const float*)d_in[8];
    const float* Wf   = (const float*)d_in[9];
    const float* bf   = (const float*)d_in[10];
    const float* Wb   = (const float*)d_in[11];
    const float* bb   = (const float*)d_in[12];
    float* out = (float*)d_out;

    float *px, *pbc, *phA, *phB, *ppart;
    cudaGetSymbolAddress((void**)&px,    g_x);
    cudaGetSymbolAddress((void**)&pbc,   g_bc);
    cudaGetSymbolAddress((void**)&phA,   g_hA);
    cudaGetSymbolAddress((void**)&phB,   g_hB);
    cudaGetSymbolAddress((void**)&ppart, g_part);

    build_x_kernel<<<MM, 256>>>(hist, nid, adj, emb);   // launch #1 (prep merged)

    constexpr int SA = 8;   // split-K for the wide-K input GEMM (blocks 1,2)
    constexpr int RED_GRID = (MM * HIDC / 4) / 256;  // 1024

    float* xin = px;
    float* bcout[3] = { pbc, px, out };

    for (int i = 0; i < 3; i++) {
        const float* wi = Win + (size_t)i * DD * HIDC;

        // h = relu(x @ W_in + b_in)
        if (i == 0) {
            // block 0: x's mid region is ~99.8% zeros -> sparse path (fp32-exact)
            fc0_kernel<<<MM, 128>>>(px, wi, bin, phA);            // #2
        } else {
            gemm_k<64, 2><<<dim3(2, 64, SA), 256>>>(xin, DP, wi, HIDC, DD, HIDC,
                                                    nullptr, nullptr, 0, ppart, HIDC);
            reduce_relu_kernel<<<RED_GRID, 256>>>(ppart, bin + i * HIDC, phA, SA);
        }

        // two hidden layers — fused bias+relu epilogue, no split-K
        gemm_k<64, 0><<<dim3(2, 64), 256>>>(phA, HIDC,           // #3
                                            Whid + (size_t)(i * 2 + 0) * HIDC * HIDC, HIDC,
                                            HIDC, HIDC, bhid + (i * 2 + 0) * HIDC,
                                            nullptr, 0, phB, HIDC);
        gemm_k<64, 0><<<dim3(2, 64), 256>>>(phB, HIDC,           // #4
                                            Whid + (size_t)(i * 2 + 1) * HIDC * HIDC, HIDC,
                                            HIDC, HIDC, bhid + (i * 2 + 1) * HIDC,
                                            nullptr, 0, phA, HIDC);

        // forecast accumulation (final block also applies * level and writes d_out tail)
        forecast_kernel<<<512, 192>>>(phA, Wf + (size_t)i * HIDC * HORC, bf + i * HORC,
                                      i, out + (size_t)MM * DD);  // #5

        // backcast = relu(x - (h @ W_b + b_b))  — BM=64 for occupancy; launch #6 = ncu target
        int ldo = (i == 2) ? DD : DP;
        gemm_k<64, 1><<<dim3(97, 64), 256>>>(phA, HIDC,
                                             Wb + (size_t)i * HIDC * DD, DD,
                                             HIDC, DD, bb + (size_t)i * DD,
                                             xin, DP, bcout[i], ldo);
        xin = bcout[i];
    }
}

// round 14
// speedup vs baseline: 1.0899x; 1.0899x over previous
#include <cuda_runtime.h>
#include <cstdint>

#define DI __device__ __forceinline__

// ---------------- problem constants ----------------
constexpr int NBN  = 512;                 // nodes
constexpr int TT   = 24;                  // T
constexpr int HIDC = 256;
constexpr int HORC = 24;
constexpr int NIDC = 64;
constexpr int DD   = TT + NBN * TT + NIDC; // 12376
constexpr int DP   = 12384;               // padded to /16 (= 774*16)
constexpr int MM   = 8 * NBN;             // 4096 rows
constexpr int SPLIT_MAX = 8;
constexpr int CAPR = 4096;                // sparse entries cap per row
constexpr int WBN  = 12416;               // padded N for W_b (97*128)

// ---------------- scratch (__device__ globals; no allocs) ----------------
__device__ float g_x   [(size_t)MM * DP];               // ~203 MB
__device__ float g_bc  [(size_t)MM * DP];               // ~203 MB
__device__ float g_part[(size_t)SPLIT_MAX * MM * HIDC]; // 33.5 MB split-K partials
__device__ int   g_scol[(size_t)MM * CAPR];
__device__ float g_sval[(size_t)MM * CAPR];
__device__ int   g_scnt[MM];
__device__ float g_hA[MM * HIDC];
__device__ float g_hB[MM * HIDC];
__device__ float g_F [MM * HORC];
__device__ float g_level[MM];
// pre-rounded (RNA tf32) + zero-padded weight copies
__device__ float g_winr[(size_t)3 * DP * HIDC];         // 38 MB
__device__ float g_wbr [(size_t)3 * HIDC * WBN];        // 38 MB
__device__ float g_whr [3 * 2 * HIDC * HIDC];           // 1.6 MB

// ---------------- helpers ----------------
DI float tf32r(float x) {                 // round-to-nearest TF32 (fp32 container)
    unsigned o;
    asm("cvt.rna.tf32.f32 %0, %1;" : "=r"(o) : "f"(x));
    return __uint_as_float(o);
}

DI void mma8(float c[4], const unsigned a[4], const unsigned b[2]) {
    asm volatile(
        "mma.sync.aligned.m16n8k8.row.col.f32.tf32.tf32.f32 "
        "{%0,%1,%2,%3}, {%4,%5,%6,%7}, {%8,%9}, {%0,%1,%2,%3};\n"
        : "+f"(c[0]), "+f"(c[1]), "+f"(c[2]), "+f"(c[3])
        : "r"(a[0]), "r"(a[1]), "r"(a[2]), "r"(a[3]),
          "r"(b[0]), "r"(b[1]));
}

DI void ldsm4(unsigned r[4], uint32_t addr) {
    asm volatile("ldmatrix.sync.aligned.m8n8.x4.shared.b16 {%0,%1,%2,%3}, [%4];"
                 : "=r"(r[0]), "=r"(r[1]), "=r"(r[2]), "=r"(r[3]) : "r"(addr));
}

DI void cpa16(uint32_t saddr, const float* g) {
    asm volatile("cp.async.ca.shared.global [%0], [%1], 16;" :: "r"(saddr), "l"(g));
}
DI void cp_commit() { asm volatile("cp.async.commit_group;"); }
DI void cp_wait1()  { asm volatile("cp.async.wait_group 1;"); }

// ---------------- weight prep: round + pad ----------------
__global__ void prep_wbh_kernel(const float* __restrict__ Wb,
                                const float* __restrict__ Whid) {
    constexpr int WB4 = 3 * HIDC * WBN / 4;      // 2,383,872
    constexpr int WH4 = 3 * 2 * HIDC * HIDC / 4; // 98,304
    int idx = blockIdx.x * 256 + threadIdx.x;
    if (idx < WB4) {
        int c4   = idx % (WBN / 4);
        int rest = idx / (WBN / 4);
        int col  = c4 * 4;
        float4 v = make_float4(0.f, 0.f, 0.f, 0.f);
        if (col < DD) {                          // DD%4==0: float4 fully in-range
            v = *reinterpret_cast<const float4*>(Wb + (size_t)rest * DD + col);
            v.x = tf32r(v.x); v.y = tf32r(v.y); v.z = tf32r(v.z); v.w = tf32r(v.w);
        }
        reinterpret_cast<float4*>(g_wbr)[idx] = v;
    } else if (idx < WB4 + WH4) {
        int j = idx - WB4;
        float4 v = reinterpret_cast<const float4*>(Whid)[j];
        v.x = tf32r(v.x); v.y = tf32r(v.y); v.z = tf32r(v.z); v.w = tf32r(v.w);
        reinterpret_cast<float4*>(g_whr)[j] = v;
    }
}

__global__ void prep_win_kernel(const float* __restrict__ Win) {
    constexpr int W4 = 3 * DP * HIDC / 4;        // 2,377,728
    int idx = blockIdx.x * 256 + threadIdx.x;
    if (idx >= W4) return;
    int n4   = idx % (HIDC / 4);
    int rest = idx / (HIDC / 4);                 // k + DP*blk
    int k    = rest % DP;
    int blk  = rest / DP;
    float4 v = make_float4(0.f, 0.f, 0.f, 0.f);
    if (k < DD) {
        v = *reinterpret_cast<const float4*>(Win + ((size_t)blk * DD + k) * HIDC + n4 * 4);
        v.x = tf32r(v.x); v.y = tf32r(v.y); v.z = tf32r(v.z); v.w = tf32r(v.w);
    }
    reinterpret_cast<float4*>(g_winr)[idx] = v;
}

// ---------------- build x = concat(hist/level, relu(adj*hist/level - 1), emb) ----------------
__global__ __launch_bounds__(256) void build_x_kernel(
        const float* __restrict__ hist, const int* __restrict__ nid,
        const float* __restrict__ adj,  const float* __restrict__ emb) {
    int r = blockIdx.x;
    const int tid = threadIdx.x;
    const float* adjr  = adj  + (size_t)r * NBN;
    const float* histb = hist + (size_t)(r >> 9) * NBN * TT;
    const float* histr = hist + (size_t)r * TT;
    float* xr = g_x + (size_t)r * DP;

    __shared__ float s_inv;
    if (tid < 32) {
        float v = (tid < TT) ? histr[tid] : -1e30f;
#pragma unroll
        for (int off = 16; off > 0; off >>= 1)
            v = fmaxf(v, __shfl_xor_sync(0xffffffffu, v, off));
        if (tid == 0) {
            g_level[r] = v;
            s_inv = (v != 0.0f) ? (1.0f / v) : 0.0f;
        }
    }
    __syncthreads();
    const float inv = s_inv;
    int nodeid = nid[r];

    for (int c4 = tid; c4 < DP / 4; c4 += blockDim.x) {
        int c = c4 * 4;
        float4 v;
        if (c < TT) {
            v.x = histr[c] * inv; v.y = histr[c + 1] * inv;
            v.z = histr[c + 2] * inv; v.w = histr[c + 3] * inv;
        } else if (c < TT + NBN * TT) {
            int u  = c - TT;
            int m  = u / TT;
            int t0 = u - m * TT;
            float a = adjr[m];
            const float* hm = histb + m * TT + t0;
            v.x = fmaxf(fmaf(a * hm[0], inv, -1.0f), 0.0f);
            v.y = fmaxf(fmaf(a * hm[1], inv, -1.0f), 0.0f);
            v.z = fmaxf(fmaf(a * hm[2], inv, -1.0f), 0.0f);
            v.w = fmaxf(fmaf(a * hm[3], inv, -1.0f), 0.0f);
        } else if (c < DD) {
            const float* e = emb + (size_t)nodeid * NIDC + (c - (TT + NBN * TT));
            v.x = e[0]; v.y = e[1]; v.z = e[2]; v.w = e[3];
        } else {
            v.x = v.y = v.z = v.w = 0.0f;
        }
        reinterpret_cast<float4*>(xr + c)[0] = v;
    }

    // ---- deterministic sparse compaction of mid region ----
    __shared__ int s_c[256];
    const int ub = tid * 48;
    int ln = 0;
    for (int i = 0; i < 48; i++) {
        int m = 2 * tid + (i >= 24 ? 1 : 0);
        int t = (i >= 24) ? i - 24 : i;
        float v = fmaxf(fmaf(adjr[m] * histb[m * TT + t], inv, -1.0f), 0.0f);
        ln += (v > 0.0f) ? 1 : 0;
    }
    s_c[tid] = ln;
    __syncthreads();
    for (int off = 1; off < 256; off <<= 1) {
        int add = (tid >= off) ? s_c[tid - off] : 0;
        __syncthreads();
        s_c[tid] += add;
        __syncthreads();
    }
    int base = s_c[tid] - ln;
    int w = 0;
    for (int i = 0; i < 48; i++) {
        int m = 2 * tid + (i >= 24 ? 1 : 0);
        int t = (i >= 24) ? i - 24 : i;
        float v = fmaxf(fmaf(adjr[m] * histb[m * TT + t], inv, -1.0f), 0.0f);
        if (v > 0.0f) {
            int pos = base + w;
            if (pos < CAPR) {
                g_scol[(size_t)r * CAPR + pos] = TT + ub + i;
                g_sval[(size_t)r * CAPR + pos] = v;
            }
            w++;
        }
    }
    if (tid == 255) g_scnt[r] = min(s_c[255], CAPR);
}

// ---------------- block-0 input layer via sparsity (fp32-exact) ----------------
__global__ __launch_bounds__(128) void fc0_kernel(
        const float* __restrict__ x, const float* __restrict__ W,
        const float* __restrict__ bias, float* __restrict__ out) {
    const int r = blockIdx.x, tid = threadIdx.x;
    __shared__ float sx[88];
    __shared__ int   scc[128];
    __shared__ float svv[128];
    if (tid < 24)       sx[tid] = x[(size_t)r * DP + tid];
    else if (tid < 88)  sx[tid] = x[(size_t)r * DP + 12312 + (tid - 24)];
    __syncthreads();

    float a0 = 0.0f, a1 = 0.0f;
#pragma unroll 8
    for (int j = 0; j < 88; j++) {
        int c = (j < 24) ? j : 12312 + (j - 24);
        float xv = sx[j];
        a0 = fmaf(xv, W[(size_t)c * HIDC + tid],       a0);
        a1 = fmaf(xv, W[(size_t)c * HIDC + tid + 128], a1);
    }
    const int cnt = g_scnt[r];
    for (int bse = 0; bse < cnt; bse += 128) {
        __syncthreads();
        if (bse + tid < cnt) {
            scc[tid] = g_scol[(size_t)r * CAPR + bse + tid];
            svv[tid] = g_sval[(size_t)r * CAPR + bse + tid];
        }
        __syncthreads();
        int m = min(128, cnt - bse);
        for (int j = 0; j < m; j++) {
            float v = svv[j];
            int   c = scc[j];
            a0 = fmaf(v, W[(size_t)c * HIDC + tid],       a0);
            a1 = fmaf(v, W[(size_t)c * HIDC + tid + 128], a1);
        }
    }
    // tf32-rounded at write: downstream GEMMs consume h directly via cp.async
    out[(size_t)r * HIDC + tid]       = tf32r(fmaxf(a0 + bias[tid],       0.0f));
    out[(size_t)r * HIDC + tid + 128] = tf32r(fmaxf(a1 + bias[tid + 128], 0.0f));
}

// ---------------- TF32 GEMM, cp.async 3-stage pipeline ----------------
// EPI 0: Out = tf32r(relu(acc + bias[n]))
// EPI 1: Out = relu(Xin - acc - bias[n])   (+ zero-fill DP pad cols)
// EPI 2: Out[z-slice] = acc                (split-K partial)
// AREG 1: A loaded via registers + RNA cvt (raw fp32 source, padded buffer)
// AREG 0: A loaded via cp.async (source already tf32-rounded, padded)
template <int BM, int EPI, int AREG>
__global__ __launch_bounds__(256) void gemm_k(
    const float* __restrict__ A, int lda,
    const float* __restrict__ B, int ldb,
    int K, int Nreal,
    const float* __restrict__ bias,
    const float* __restrict__ Xin, int ldx,
    float* __restrict__ Out, int ldo)
{
    constexpr int BN = 128, KT = 16;
    constexpr int WM = BM / 2;
    constexpr int MT = WM / 16;
    constexpr int NA   = AREG ? 2 : 3;
    constexpr int ASTR = BM * 20 * 4;
    constexpr int BSTR = KT * 136 * 4;
    constexpr int ATOT = NA * ASTR;
    constexpr int PIPEB  = ATOT + 3 * BSTR;
    constexpr int CBYTES = 64 * 132 * 4;
    constexpr int RAWB   = PIPEB > CBYTES ? PIPEB : CBYTES;

    __shared__ __align__(16) char raw[RAWB];
    const uint32_t sbase = (uint32_t)__cvta_generic_to_shared(raw);

    const int tid  = threadIdx.x;
    const int warp = tid >> 5, lane = tid & 31;
    const int wm = warp >> 2, wn = warp & 3;
    const int gid = lane >> 2, tig = lane & 3;
    const int m0 = blockIdx.y * BM;
    const int n0 = blockIdx.x * BN;
    const int lt = lane >> 3, lr = lane & 7;
    const uint32_t aAddr0 = sbase +
        (uint32_t)(((wm * WM + lr + ((lt & 1) << 3)) * 20 + ((lt >> 1) << 2)) * 4);

    float acc[MT][4][4];
#pragma unroll
    for (int mi = 0; mi < MT; mi++)
#pragma unroll
        for (int ni = 0; ni < 4; ni++)
#pragma unroll
            for (int e = 0; e < 4; e++) acc[mi][ni][e] = 0.0f;

    const int arow = tid >> 2;                // 0..63
    const int akc  = (tid & 3) * 4;

    auto cpA = [&](int kt, int st) {
        cpa16(sbase + st * ASTR + (arow * 20 + akc) * 4,
              A + (size_t)(m0 + arow) * lda + kt * KT + akc);
    };
    auto cpB = [&](int kt, int st) {
#pragma unroll
        for (int i2 = 0; i2 < 2; i2++) {
            int j = tid + i2 * 256, kr = j >> 5, cf = (j & 31) * 4;
            cpa16(sbase + ATOT + st * BSTR + (kr * 136 + cf) * 4,
                  B + (size_t)(kt * KT + kr) * ldb + n0 + cf);
        }
    };
    float4 aR[3];
    auto ldgA = [&](int kt, int sl) {
        aR[sl] = *reinterpret_cast<const float4*>(A + (size_t)(m0 + arow) * lda + kt * KT + akc);
    };
    auto stsA = [&](int st, int sl) {
        float4 v = aR[sl];
        v.x = tf32r(v.x); v.y = tf32r(v.y); v.z = tf32r(v.z); v.w = tf32r(v.w);
        *reinterpret_cast<float4*>(raw + st * ASTR + (arow * 20 + akc) * 4) = v;
    };

    auto compute = [&](int sa, int sb) {
        const uint32_t ap = aAddr0 + (uint32_t)(sa * ASTR);
        const float* Bp = reinterpret_cast<const float*>(raw + ATOT + sb * BSTR);
#pragma unroll
        for (int sub = 0; sub < 2; sub++) {
            int kb = sub * 8;
            unsigned af[MT][4];
#pragma unroll
            for (int mi = 0; mi < MT; mi++)
                ldsm4(af[mi], ap + mi * (16 * 20 * 4) + sub * 32);
            unsigned bfr[4][2];
#pragma unroll
            for (int ni = 0; ni < 4; ni++) {
                int c = wn * 32 + ni * 8 + gid;
                bfr[ni][0] = __float_as_uint(Bp[(kb + tig) * 136 + c]);
                bfr[ni][1] = __float_as_uint(Bp[(kb + tig + 4) * 136 + c]);
            }
#pragma unroll
            for (int mi = 0; mi < MT; mi++)
#pragma unroll
                for (int ni = 0; ni < 4; ni++)
                    mma8(acc[mi][ni], af[mi], bfr[ni]);
        }
    };

    const int nk_total = (K + KT - 1) / KT;
    const int per = (nk_total + gridDim.z - 1) / gridDim.z;
    const int kt0 = blockIdx.z * per;
    const int kt1 = min(nk_total, kt0 + per);

    // ---- prologue: tiles kt0, kt0+1 in flight (distance 2; A regs distance 3) ----
    if (AREG) {
        ldgA(kt0, 0);
        if (kt0 + 1 < kt1) ldgA(kt0 + 1, 1);
        if (kt0 + 2 < kt1) ldgA(kt0 + 2, 2);
        stsA(0, 0);
        cpB(kt0, 0); cp_commit();
        if (kt0 + 1 < kt1) cpB(kt0 + 1, 1);
        cp_commit();
    } else {
        cpA(kt0, 0); cpB(kt0, 0); cp_commit();
        if (kt0 + 1 < kt1) { cpA(kt0 + 1, 1); cpB(kt0 + 1, 1); }
        cp_commit();
    }
    cp_wait1();
    __syncthreads();

    for (int kt = kt0; kt < kt1; kt++) {
        const int i = kt - kt0;
        if (AREG) {
            if (kt + 1 < kt1) stsA((i + 1) & 1, (i + 1) % 3);
            if (kt + 2 < kt1) cpB(kt + 2, (i + 2) % 3);
            cp_commit();
            if (kt + 3 < kt1) ldgA(kt + 3, i % 3);
            compute(i & 1, i % 3);
        } else {
            if (kt + 2 < kt1) { cpA(kt + 2, (i + 2) % 3); cpB(kt + 2, (i + 2) % 3); }
            cp_commit();
            compute(i % 3, i % 3);
        }
        cp_wait1();
        __syncthreads();
    }

    // ---------------- staged, fully-coalesced epilogue ----------------
    const size_t zoff = (EPI == 2) ? (size_t)blockIdx.z * MM * HIDC : 0;
    float* Cs = reinterpret_cast<float*>(raw);
#pragma unroll
    for (int half = 0; half < BM / 64; half++) {
        if (((wm * WM) >> 6) == half) {
#pragma unroll
            for (int mi = 0; mi < MT; mi++)
#pragma unroll
                for (int ni = 0; ni < 4; ni++)
#pragma unroll
                    for (int e = 0; e < 4; e++) {
                        int rl = wm * WM + mi * 16 + gid + ((e >> 1) << 3) - half * 64;
                        int cl = wn * 32 + ni * 8 + tig * 2 + (e & 1);
                        Cs[rl * 132 + cl] = acc[mi][ni][e];
                    }
        }
        __syncthreads();
#pragma unroll
        for (int j = 0; j < 8; j++) {
            int idx = tid + j * 256;
            int rl = idx >> 5, c4 = idx & 31;
            int row = m0 + half * 64 + rl;
            int gc  = n0 + c4 * 4;
            if (gc + 4 <= Nreal) {
                float4 a = *reinterpret_cast<const float4*>(&Cs[rl * 132 + c4 * 4]);
                if (EPI == 0) {
                    float4 bv = *reinterpret_cast<const float4*>(bias + gc);
                    float4 r;
                    r.x = tf32r(fmaxf(a.x + bv.x, 0.0f));
                    r.y = tf32r(fmaxf(a.y + bv.y, 0.0f));
                    r.z = tf32r(fmaxf(a.z + bv.z, 0.0f));
                    r.w = tf32r(fmaxf(a.w + bv.w, 0.0f));
                    *reinterpret_cast<float4*>(Out + (size_t)row * ldo + gc) = r;
                } else if (EPI == 1) {
                    float4 xv = *reinterpret_cast<const float4*>(Xin + (size_t)row * ldx + gc);
                    float4 bv = *reinterpret_cast<const float4*>(bias + gc);
                    float4 r;
                    r.x = fmaxf(xv.x - a.x - bv.x, 0.0f);
                    r.y = fmaxf(xv.y - a.y - bv.y, 0.0f);
                    r.z = fmaxf(xv.z - a.z - bv.z, 0.0f);
                    r.w = fmaxf(xv.w - a.w - bv.w, 0.0f);
                    *reinterpret_cast<float4*>(Out + (size_t)row * ldo + gc) = r;
                } else {
                    *reinterpret_cast<float4*>(Out + zoff + (size_t)row * ldo + gc) = a;
                }
            } else if (EPI == 1 && gc + 4 <= ldo) {
                // zero-fill DP pad cols so guard-free A loads never see poison
                *reinterpret_cast<float4*>(Out + (size_t)row * ldo + gc) =
                    make_float4(0.f, 0.f, 0.f, 0.f);
            }
        }
        __syncthreads();
    }
}

// ---------------- split-K reduce: out = tf32r(relu(sum_s part[s] + bias)) ----------------
__global__ void reduce_relu_kernel(const float* __restrict__ part,
                                   const float* __restrict__ bias,
                                   float* __restrict__ out, int S) {
    int idx = blockIdx.x * blockDim.x + threadIdx.x;
    const float4* p4 = reinterpret_cast<const float4*>(part);
    size_t stride4 = (size_t)MM * HIDC / 4;
    float4 a = p4[idx];
    for (int s = 1; s < S; s++) {
        float4 b = p4[idx + (size_t)s * stride4];
        a.x += b.x; a.y += b.y; a.z += b.z; a.w += b.w;
    }
    int col = (idx * 4) & (HIDC - 1);
    float4 bv = *reinterpret_cast<const float4*>(bias + col);
    float4 r;
    r.x = tf32r(fmaxf(a.x + bv.x, 0.0f));
    r.y = tf32r(fmaxf(a.y + bv.y, 0.0f));
    r.z = tf32r(fmaxf(a.z + bv.z, 0.0f));
    r.w = tf32r(fmaxf(a.w + bv.w, 0.0f));
    reinterpret_cast<float4*>(out)[idx] = r;
}

// ---------------- forecast: F (+)= h @ W_f + b_f ; final: out = F * level ----------------
__global__ void forecast_kernel(const float* __restrict__ h, const float* __restrict__ Wf,
                                const float* __restrict__ bf, int mode,
                                float* __restrict__ outF) {
    __shared__ float sW[HIDC * HORC];
    for (int i = threadIdx.x; i < HIDC * HORC; i += blockDim.x) sW[i] = Wf[i];
    __syncthreads();
    int idx = blockIdx.x * blockDim.x + threadIdx.x;
    int r = idx / HORC, o = idx - r * HORC;
    const float* hr = h + (size_t)r * HIDC;
    float a = 0.0f;
#pragma unroll 8
    for (int k = 0; k < HIDC; k++) a = fmaf(hr[k], sW[k * HORC + o], a);
    a += bf[o];
    if (mode == 0)      g_F[idx] = a;
    else if (mode == 1) g_F[idx] += a;
    else                outF[idx] = (g_F[idx] + a) * g_level[r];
}

// ---------------- launch ----------------
extern "C" void kernel_launch(void* const* d_in, const int* in_sizes, int n_in,
                              void* d_out, int out_size) {
    const float* hist = (const float*)d_in[0];
    const int*   nid  = (const int*)  d_in[1];
    const float* adj  = (const float*)d_in[3];
    const float* emb  = (const float*)d_in[4];
    const float* Win  = (const float*)d_in[5];
    const float* bin  = (const float*)d_in[6];
    const float* Whid = (const float*)d_in[7];
    const float* bhid = (const float*)d_in[8];
    const float* Wf   = (const float*)d_in[9];
    const float* bf   = (const float*)d_in[10];
    const float* Wb   = (const float*)d_in[11];
    const float* bb   = (const float*)d_in[12];
    float* out = (float*)d_out;

    float *px, *pbc, *phA, *phB, *ppart, *pwinr, *pwbr, *pwhr;
    cudaGetSymbolAddress((void**)&px,    g_x);
    cudaGetSymbolAddress((void**)&pbc,   g_bc);
    cudaGetSymbolAddress((void**)&phA,   g_hA);
    cudaGetSymbolAddress((void**)&phB,   g_hB);
    cudaGetSymbolAddress((void**)&ppart, g_part);
    cudaGetSymbolAddress((void**)&pwinr, g_winr);
    cudaGetSymbolAddress((void**)&pwbr,  g_wbr);
    cudaGetSymbolAddress((void**)&pwhr,  g_whr);

    constexpr int SA = 8;
    constexpr int RED_GRID = (MM * HIDC / 4) / 256;  // 1024
    constexpr int WBH_GRID = (3 * HIDC * WBN / 4 + 3 * 2 * HIDC * HIDC / 4 + 255) / 256;
    constexpr int WIN_GRID = (3 * DP * HIDC / 4 + 255) / 256;

    build_x_kernel<<<MM, 256>>>(hist, nid, adj, emb);          // #1
    fc0_kernel<<<MM, 128>>>(px, Win, bin, phA);                // #2 (raw Win, fp32-exact)
    prep_wbh_kernel<<<WBH_GRID, 256>>>(Wb, Whid);              // #3

    float* xin = px;
    float* bcout[3] = { pbc, px, out };

    for (int i = 0; i < 3; i++) {
        if (i > 0) {
            // h = relu(bc @ W_in + b_in): AREG path (raw bc, cvt in regs), split-K
            gemm_k<64, 2, 1><<<dim3(2, 64, SA), 256>>>(
                xin, DP, pwinr + (size_t)i * DP * HIDC, HIDC, DD, HIDC,
                nullptr, nullptr, 0, ppart, HIDC);
            reduce_relu_kernel<<<RED_GRID, 256>>>(ppart, bin + i * HIDC, phA, SA);
        }

        // two hidden layers: cp.async both operands, fused bias+relu (rounded write)
        gemm_k<64, 0, 0><<<dim3(2, 64), 256>>>(
            phA, HIDC, pwhr + (size_t)(i * 2 + 0) * HIDC * HIDC, HIDC,
            HIDC, HIDC, bhid + (i * 2 + 0) * HIDC, nullptr, 0, phB, HIDC);  // #4
        gemm_k<64, 0, 0><<<dim3(2, 64), 256>>>(
            phB, HIDC, pwhr + (size_t)(i * 2 + 1) * HIDC * HIDC, HIDC,
            HIDC, HIDC, bhid + (i * 2 + 1) * HIDC, nullptr, 0, phA, HIDC);  // #5

        // backcast = relu(x - (h @ W_b + b_b)): cp.async, padded W_b      // #6 = ncu target
        int ldo = (i == 2) ? DD : DP;
        gemm_k<64, 1, 0><<<dim3(97, 64), 256>>>(
            phA, HIDC, pwbr + (size_t)i * HIDC * WBN, WBN,
            HIDC, DD, bb + (size_t)i * DD, xin, DP, bcout[i], ldo);

        // forecast accumulation (reads phA only; safe after backcast)
        forecast_kernel<<<512, 192>>>(phA, Wf + (size_t)i * HIDC * HORC, bf + i * HORC,
                                      i, out + (size_t)MM * DD);

        if (i == 0) prep_win_kernel<<<WIN_GRID, 256>>>(Win);   // needed before block-1 GEMM-A

        xin = bcout[i];
    }
}